// round 1
// baseline (speedup 1.0000x reference)
#include <cuda_runtime.h>
#include <mma.h>
#include <math.h>

using namespace nvcuda;

#define HH 512
#define SS 6
#define MAXB 16384
#define KC 528      // comb K: 512 attn_applied + input col + bias col + pad to 16
#define KG 1040     // gates K: 512 x + 512 hidden + bias col + pad to 16

// ---- scratch (static device globals; no runtime allocation) ----
__device__ __align__(16) float g_Xc  [(size_t)MAXB * KC];   // comb GEMM A
__device__ __align__(16) float g_Abig[(size_t)MAXB * KG];   // gates GEMM A: [x | hidden | 1 | 0pad]
__device__ __align__(16) float g_gates[(size_t)MAXB * 4 * HH];
__device__ __align__(16) float g_Wc  [HH * KC];             // [Wcomb[:,1:513] | Wcomb[:,0] | bcomb | 0]
__device__ __align__(16) float g_Wg  [4 * HH * KG];         // [W_ih | W_hh | b_ih+b_hh | 0]

// ---- build padded weight matrices (runs every launch; deterministic) ----
__global__ void init_weights(const float* __restrict__ Wcomb, const float* __restrict__ bcomb,
                             const float* __restrict__ Wih,   const float* __restrict__ Whh,
                             const float* __restrict__ bih,   const float* __restrict__ bhh) {
    int idx = blockIdx.x * blockDim.x + threadIdx.x;
    int stride = gridDim.x * blockDim.x;
    for (int i = idx; i < HH * KC; i += stride) {
        int n = i / KC, k = i % KC;
        float v = 0.f;
        if (k < 512)        v = Wcomb[n * 513 + 1 + k];
        else if (k == 512)  v = Wcomb[n * 513];
        else if (k == 513)  v = bcomb[n];
        g_Wc[i] = v;
    }
    for (int i = idx; i < 4 * HH * KG; i += stride) {
        int n = i / KG, k = i % KG;
        float v = 0.f;
        if (k < 512)        v = Wih[n * 512 + k];
        else if (k < 1024)  v = Whh[n * 512 + (k - 512)];
        else if (k == 1024) v = bih[n] + bhh[n];
        g_Wg[i] = v;
    }
}

// ---- attention: logits -> softmax -> weighted sum; also builds GEMM A operands ----
__global__ void attn_kernel(const float* __restrict__ input, const float* __restrict__ hidden,
                            const float* __restrict__ cell,  const float* __restrict__ enc,
                            const float* __restrict__ Wattn, const float* __restrict__ battn,
                            float* __restrict__ out_attnw) {
    int b = blockIdx.x;
    int tid = threadIdx.x;             // 256 threads
    __shared__ float s_w[SS];
    __shared__ float s_part[8][SS];

    float h0 = hidden[(size_t)b * HH + tid];
    float h1 = hidden[(size_t)b * HH + tid + 256];
    float c0 = cell  [(size_t)b * HH + tid];
    float c1 = cell  [(size_t)b * HH + tid + 256];

    float p[SS];
#pragma unroll
    for (int s = 0; s < SS; s++) {
        const float* wr = Wattn + s * 1025;
        p[s] = wr[1 + tid] * h0 + wr[1 + tid + 256] * h1
             + wr[513 + tid] * c0 + wr[513 + tid + 256] * c1;
    }
#pragma unroll
    for (int s = 0; s < SS; s++)
#pragma unroll
        for (int off = 16; off; off >>= 1)
            p[s] += __shfl_down_sync(0xffffffffu, p[s], off);
    int warp = tid >> 5, lane = tid & 31;
    if (lane == 0)
#pragma unroll
        for (int s = 0; s < SS; s++) s_part[warp][s] = p[s];
    __syncthreads();

    if (tid == 0) {
        float inp = input[b];
        float lg[SS], mx = -1e30f;
#pragma unroll
        for (int s = 0; s < SS; s++) {
            float v = battn[s] + Wattn[s * 1025] * inp;
#pragma unroll
            for (int w = 0; w < 8; w++) v += s_part[w][s];
            lg[s] = v; mx = fmaxf(mx, v);
        }
        float sum = 0.f;
#pragma unroll
        for (int s = 0; s < SS; s++) { lg[s] = expf(lg[s] - mx); sum += lg[s]; }
        float inv = 1.f / sum;
#pragma unroll
        for (int s = 0; s < SS; s++) {
            float w = lg[s] * inv;
            s_w[s] = w;
            out_attnw[(size_t)b * SS + s] = w;
        }
    }
    __syncthreads();

    float w0 = s_w[0], w1 = s_w[1], w2 = s_w[2], w3 = s_w[3], w4 = s_w[4], w5 = s_w[5];
    const float* eb = enc + (size_t)b * SS * HH;
#pragma unroll
    for (int r = 0; r < 2; r++) {
        int k = tid + r * 256;
        float a = w0 * eb[k]          + w1 * eb[HH + k]     + w2 * eb[2 * HH + k]
                + w3 * eb[3 * HH + k] + w4 * eb[4 * HH + k] + w5 * eb[5 * HH + k];
        g_Xc  [(size_t)b * KC + k] = a;
        g_Abig[(size_t)b * KG + 512 + k] = (r == 0) ? h0 : h1;
    }
    if (tid == 0) {
        g_Xc  [(size_t)b * KC + 512] = input[b];
        g_Xc  [(size_t)b * KC + 513] = 1.f;
        g_Abig[(size_t)b * KG + 1024] = 1.f;
    }
    if (tid >= 2 && tid < 16) g_Xc  [(size_t)b * KC + 512 + tid] = 0.f;
    if (tid >= 1 && tid < 16) g_Abig[(size_t)b * KG + 1024 + tid] = 0.f;
}

// ---- tf32 wmma GEMM: C[M,N] = op(A[M,K] @ W[N,K]^T), 128x128 tile / 8 warps ----
template <bool RELU>
__global__ void __launch_bounds__(256, 2)
gemm_tf32(const float* __restrict__ A, int lda,
          const float* __restrict__ Bw, int ldb,
          float* __restrict__ C, int ldc, int K) {
    constexpr int BM = 128, BN = 128, BK = 16, PAD = 20;
    __shared__ float As[BM * PAD];
    __shared__ float Bs[BN * PAD];
    int m0 = blockIdx.y * BM, n0 = blockIdx.x * BN;
    int tid = threadIdx.x;
    int warp = tid >> 5;
    int wr = warp & 1;    // 0..1  -> 64-row slab
    int wc = warp >> 1;   // 0..3  -> 32-col slab

    wmma::fragment<wmma::accumulator, 16, 16, 8, float> acc[4][2];
#pragma unroll
    for (int i = 0; i < 4; i++)
#pragma unroll
        for (int j = 0; j < 2; j++) wmma::fill_fragment(acc[i][j], 0.f);

    for (int k0 = 0; k0 < K; k0 += BK) {
        __syncthreads();
#pragma unroll
        for (int i = 0; i < 2; i++) {
            int q = tid + i * 256;            // float4 index, 512 total per operand
            int row = q >> 2, kc = (q & 3) << 2;
            float4 av = *(const float4*)&A [(size_t)(m0 + row) * lda + k0 + kc];
            *(float4*)&As[row * PAD + kc] = av;
            float4 bv = *(const float4*)&Bw[(size_t)(n0 + row) * ldb + k0 + kc];
            *(float4*)&Bs[row * PAD + kc] = bv;
        }
        __syncthreads();
#pragma unroll
        for (int kk = 0; kk < BK; kk += 8) {
            wmma::fragment<wmma::matrix_a, 16, 16, 8, wmma::precision::tf32, wmma::row_major> af[4];
            wmma::fragment<wmma::matrix_b, 16, 16, 8, wmma::precision::tf32, wmma::col_major> bf[2];
#pragma unroll
            for (int i = 0; i < 4; i++) {
                wmma::load_matrix_sync(af[i], &As[(wr * 64 + i * 16) * PAD + kk], PAD);
#pragma unroll
                for (int t = 0; t < af[i].num_elements; t++)
                    af[i].x[t] = wmma::__float_to_tf32(af[i].x[t]);
            }
#pragma unroll
            for (int j = 0; j < 2; j++) {
                wmma::load_matrix_sync(bf[j], &Bs[(wc * 32 + j * 16) * PAD + kk], PAD);
#pragma unroll
                for (int t = 0; t < bf[j].num_elements; t++)
                    bf[j].x[t] = wmma::__float_to_tf32(bf[j].x[t]);
            }
#pragma unroll
            for (int i = 0; i < 4; i++)
#pragma unroll
                for (int j = 0; j < 2; j++)
                    wmma::mma_sync(acc[i][j], af[i], bf[j], acc[i][j]);
        }
    }

#pragma unroll
    for (int i = 0; i < 4; i++)
#pragma unroll
        for (int j = 0; j < 2; j++) {
            if (RELU)
#pragma unroll
                for (int t = 0; t < acc[i][j].num_elements; t++)
                    acc[i][j].x[t] = fmaxf(acc[i][j].x[t], 0.f);
            wmma::store_matrix_sync(
                &C[(size_t)(m0 + wr * 64 + i * 16) * ldc + n0 + wc * 32 + j * 16],
                acc[i][j], ldc, wmma::mem_row_major);
        }
}

// ---- LSTM elementwise + output dot ----
__global__ void lstm_kernel(const float* __restrict__ cell, const float* __restrict__ Wout,
                            const float* __restrict__ bout,
                            float* __restrict__ out_output, float* __restrict__ out_h,
                            float* __restrict__ out_c) {
    int b = blockIdx.x, j = threadIdx.x;   // 512 threads
    const float* g = g_gates + (size_t)b * 2048;
    float gi = g[j], gf = g[512 + j], gg = g[1024 + j], go = g[1536 + j];
    float c_old = cell[(size_t)b * HH + j];
    float si = 1.f / (1.f + expf(-gi));
    float sf = 1.f / (1.f + expf(-gf));
    float so = 1.f / (1.f + expf(-go));
    float tg = tanhf(gg);
    float cn = sf * c_old + si * tg;
    float hn = so * tanhf(cn);
    out_c[(size_t)b * HH + j] = cn;
    out_h[(size_t)b * HH + j] = hn;

    float part = hn * Wout[j];
#pragma unroll
    for (int off = 16; off; off >>= 1) part += __shfl_down_sync(0xffffffffu, part, off);
    __shared__ float sp[16];
    if ((j & 31) == 0) sp[j >> 5] = part;
    __syncthreads();
    if (j < 16) {
        float v = sp[j];
#pragma unroll
        for (int off = 8; off; off >>= 1) v += __shfl_down_sync(0xffffu, v, off);
        if (j == 0) out_output[b] = v + bout[0];
    }
}

extern "C" void kernel_launch(void* const* d_in, const int* in_sizes, int n_in,
                              void* d_out, int out_size) {
    const float* input  = (const float*)d_in[0];
    const float* hidden = (const float*)d_in[1];
    const float* cell   = (const float*)d_in[2];
    const float* enc    = (const float*)d_in[3];
    const float* Wattn  = (const float*)d_in[4];
    const float* battn  = (const float*)d_in[5];
    const float* Wcomb  = (const float*)d_in[6];
    const float* bcomb  = (const float*)d_in[7];
    const float* Wih    = (const float*)d_in[8];
    const float* Whh    = (const float*)d_in[9];
    const float* bih    = (const float*)d_in[10];
    const float* bhh    = (const float*)d_in[11];
    const float* Wout   = (const float*)d_in[12];
    const float* bout   = (const float*)d_in[13];

    int B = in_sizes[1] / HH;   // 16384

    float* out      = (float*)d_out;
    float* o_output = out;                              // [B, 1]
    float* o_h      = out + (size_t)B;                  // [B, H]
    float* o_c      = o_h + (size_t)B * HH;             // [B, H]
    float* o_aw     = o_c + (size_t)B * HH;             // [B, 1, S]

    float *pXc, *pAbig, *pGates, *pWc, *pWg;
    cudaGetSymbolAddress((void**)&pXc,    g_Xc);
    cudaGetSymbolAddress((void**)&pAbig,  g_Abig);
    cudaGetSymbolAddress((void**)&pGates, g_gates);
    cudaGetSymbolAddress((void**)&pWc,    g_Wc);
    cudaGetSymbolAddress((void**)&pWg,    g_Wg);

    init_weights<<<512, 256>>>(Wcomb, bcomb, Wih, Whh, bih, bhh);
    attn_kernel<<<B, 256>>>(input, hidden, cell, enc, Wattn, battn, o_aw);

    // comb: Abig[:, 0:512] = relu(Xc @ Wc^T)   (input col + bias folded into K)
    {
        dim3 grid(HH / 128, B / 128);
        gemm_tf32<true><<<grid, 256>>>(pXc, KC, pWc, KC, pAbig, KG, KC);
    }
    // gates = Abig @ Wg^T   ([x | hidden | 1] against [W_ih | W_hh | b_ih+b_hh])
    {
        dim3 grid((4 * HH) / 128, B / 128);
        gemm_tf32<false><<<grid, 256>>>(pAbig, KG, pWg, KG, pGates, 4 * HH, KG);
    }
    lstm_kernel<<<B, 512>>>(cell, Wout, bout, o_output, o_h, o_c);
}

// round 5
// speedup vs baseline: 1.0699x; 1.0699x over previous
#include <cuda_runtime.h>
#include <cstdint>
#include <mma.h>
#include <math.h>

using namespace nvcuda;

#define HH 512
#define SS 6
#define MAXB 16384
#define KC 544      // comb K: 512 attn_applied + input col + bias col + pad to 32
#define KG 1056     // gates K: 512 x + 512 hidden + bias col + pad to 32

// ---- scratch (static device globals; no runtime allocation) ----
__device__ __align__(16) float g_Xc  [(size_t)MAXB * KC];   // comb GEMM A
__device__ __align__(16) float g_Abig[(size_t)MAXB * KG];   // gates GEMM A: [x | hidden | 1 | 0pad]
__device__ __align__(16) float g_gates[(size_t)MAXB * 4 * HH];
__device__ __align__(16) float g_Wc  [HH * KC];             // [Wcomb[:,1:513] | Wcomb[:,0] | bcomb | 0]
__device__ __align__(16) float g_Wg  [4 * HH * KG];         // [W_ih | W_hh | b_ih+b_hh | 0]

__device__ __forceinline__ float to_tf32(float x) {
    float r; asm("cvt.rna.tf32.f32 %0, %1;" : "=f"(r) : "f"(x)); return r;
}

// ---- build padded weight matrices, pre-rounded to tf32 ----
__global__ void init_weights(const float* __restrict__ Wcomb, const float* __restrict__ bcomb,
                             const float* __restrict__ Wih,   const float* __restrict__ Whh,
                             const float* __restrict__ bih,   const float* __restrict__ bhh) {
    int idx = blockIdx.x * blockDim.x + threadIdx.x;
    int stride = gridDim.x * blockDim.x;
    for (int i = idx; i < HH * KC; i += stride) {
        int n = i / KC, k = i % KC;
        float v = 0.f;
        if (k < 512)        v = Wcomb[n * 513 + 1 + k];
        else if (k == 512)  v = Wcomb[n * 513];
        else if (k == 513)  v = bcomb[n];
        g_Wc[i] = to_tf32(v);
    }
    for (int i = idx; i < 4 * HH * KG; i += stride) {
        int n = i / KG, k = i % KG;
        float v = 0.f;
        if (k < 512)        v = Wih[n * 512 + k];
        else if (k < 1024)  v = Whh[n * 512 + (k - 512)];
        else if (k == 1024) v = bih[n] + bhh[n];
        g_Wg[i] = to_tf32(v);
    }
}

// ---- attention: logits -> softmax -> weighted sum; builds GEMM A operands (tf32-rounded) ----
__global__ void attn_kernel(const float* __restrict__ input, const float* __restrict__ hidden,
                            const float* __restrict__ cell,  const float* __restrict__ enc,
                            const float* __restrict__ Wattn, const float* __restrict__ battn,
                            float* __restrict__ out_attnw) {
    int b = blockIdx.x;
    int tid = threadIdx.x;             // 256 threads
    __shared__ float s_w[SS];
    __shared__ float s_part[8][SS];

    float h0 = hidden[(size_t)b * HH + tid];
    float h1 = hidden[(size_t)b * HH + tid + 256];
    float c0 = cell  [(size_t)b * HH + tid];
    float c1 = cell  [(size_t)b * HH + tid + 256];

    float p[SS];
#pragma unroll
    for (int s = 0; s < SS; s++) {
        const float* wr = Wattn + s * 1025;
        p[s] = wr[1 + tid] * h0 + wr[1 + tid + 256] * h1
             + wr[513 + tid] * c0 + wr[513 + tid + 256] * c1;
    }
#pragma unroll
    for (int s = 0; s < SS; s++)
#pragma unroll
        for (int off = 16; off; off >>= 1)
            p[s] += __shfl_down_sync(0xffffffffu, p[s], off);
    int warp = tid >> 5, lane = tid & 31;
    if (lane == 0)
#pragma unroll
        for (int s = 0; s < SS; s++) s_part[warp][s] = p[s];
    __syncthreads();

    if (tid == 0) {
        float inp = input[b];
        float lg[SS], mx = -1e30f;
#pragma unroll
        for (int s = 0; s < SS; s++) {
            float v = battn[s] + Wattn[s * 1025] * inp;
#pragma unroll
            for (int w = 0; w < 8; w++) v += s_part[w][s];
            lg[s] = v; mx = fmaxf(mx, v);
        }
        float sum = 0.f;
#pragma unroll
        for (int s = 0; s < SS; s++) { lg[s] = expf(lg[s] - mx); sum += lg[s]; }
        float inv = 1.f / sum;
#pragma unroll
        for (int s = 0; s < SS; s++) {
            float w = lg[s] * inv;
            s_w[s] = w;
            out_attnw[(size_t)b * SS + s] = w;
        }
    }
    __syncthreads();

    float w0 = s_w[0], w1 = s_w[1], w2 = s_w[2], w3 = s_w[3], w4 = s_w[4], w5 = s_w[5];
    const float* eb = enc + (size_t)b * SS * HH;
#pragma unroll
    for (int r = 0; r < 2; r++) {
        int k = tid + r * 256;
        float a = w0 * eb[k]          + w1 * eb[HH + k]     + w2 * eb[2 * HH + k]
                + w3 * eb[3 * HH + k] + w4 * eb[4 * HH + k] + w5 * eb[5 * HH + k];
        g_Xc  [(size_t)b * KC + k] = to_tf32(a);
        g_Abig[(size_t)b * KG + 512 + k] = to_tf32((r == 0) ? h0 : h1);
    }
    // tail columns: Xc[512]=input, Xc[513]=1, rest 0; Abig[1024]=1, rest 0
    if (tid < 32) {
        float v = 0.f;
        if (tid == 0) v = to_tf32(input[b]);
        else if (tid == 1) v = 1.f;
        g_Xc[(size_t)b * KC + 512 + tid] = v;
        float u = (tid == 0) ? 1.f : 0.f;
        g_Abig[(size_t)b * KG + 1024 + tid] = u;
    }
}

// ---- tf32 wmma GEMM, 128x128 tile, BK=32, 2-stage cp.async double buffer ----
#define CP16(dst_u32, src_ptr) \
    asm volatile("cp.async.cg.shared.global [%0], [%1], 16;" :: "r"(dst_u32), "l"(src_ptr))

template <bool RELU>
__global__ void __launch_bounds__(256, 2)
gemm_tf32(const float* __restrict__ A, int lda,
          const float* __restrict__ Bw, int ldb,
          float* __restrict__ C, int ldc, int K) {
    constexpr int BM = 128, BN = 128, BK = 32, PAD = 36;
    extern __shared__ float smem[];
    float* As = smem;                     // 2 stages * BM*PAD
    float* Bs = smem + 2 * BM * PAD;      // 2 stages * BN*PAD

    int m0 = blockIdx.y * BM, n0 = blockIdx.x * BN;
    int tid = threadIdx.x;
    int warp = tid >> 5;
    int wr = warp & 1;    // 0..1  -> 64-row slab
    int wc = warp >> 1;   // 0..3  -> 32-col slab

    wmma::fragment<wmma::accumulator, 16, 16, 8, float> acc[4][2];
#pragma unroll
    for (int i = 0; i < 4; i++)
#pragma unroll
        for (int j = 0; j < 2; j++) wmma::fill_fragment(acc[i][j], 0.f);

    int nk = K / BK;

    // stage copy: 1024 float4 per operand, 4 per thread per operand
    auto stage_copy = [&](int st, int k0) {
#pragma unroll
        for (int i = 0; i < 4; i++) {
            int q = tid + i * 256;
            int row = q >> 3, c4 = (q & 7) << 2;
            const float* ga = &A[(size_t)(m0 + row) * lda + k0 + c4];
            unsigned int sa = (unsigned int)__cvta_generic_to_shared(&As[st * BM * PAD + row * PAD + c4]);
            CP16(sa, ga);
            const float* gb = &Bw[(size_t)(n0 + row) * ldb + k0 + c4];
            unsigned int sb = (unsigned int)__cvta_generic_to_shared(&Bs[st * BN * PAD + row * PAD + c4]);
            CP16(sb, gb);
        }
        asm volatile("cp.async.commit_group;");
    };

    stage_copy(0, 0);

    for (int t = 0; t < nk; t++) {
        if (t + 1 < nk) {
            stage_copy((t + 1) & 1, (t + 1) * BK);
            asm volatile("cp.async.wait_group 1;");
        } else {
            asm volatile("cp.async.wait_group 0;");
        }
        __syncthreads();

        const float* Ab = &As[(t & 1) * BM * PAD];
        const float* Bb = &Bs[(t & 1) * BN * PAD];
#pragma unroll
        for (int kk = 0; kk < BK; kk += 8) {
            wmma::fragment<wmma::matrix_a, 16, 16, 8, wmma::precision::tf32, wmma::row_major> af[4];
            wmma::fragment<wmma::matrix_b, 16, 16, 8, wmma::precision::tf32, wmma::col_major> bf[2];
#pragma unroll
            for (int i = 0; i < 4; i++)
                wmma::load_matrix_sync(af[i], &Ab[(wr * 64 + i * 16) * PAD + kk], PAD);
#pragma unroll
            for (int j = 0; j < 2; j++)
                wmma::load_matrix_sync(bf[j], &Bb[(wc * 32 + j * 16) * PAD + kk], PAD);
#pragma unroll
            for (int i = 0; i < 4; i++)
#pragma unroll
                for (int j = 0; j < 2; j++)
                    wmma::mma_sync(acc[i][j], af[i], bf[j], acc[i][j]);
        }
        __syncthreads();   // protect buffer (t&1) before it is refilled at iter t+1
    }

#pragma unroll
    for (int i = 0; i < 4; i++)
#pragma unroll
        for (int j = 0; j < 2; j++) {
            if (RELU)
#pragma unroll
                for (int t = 0; t < acc[i][j].num_elements; t++)
                    acc[i][j].x[t] = fmaxf(acc[i][j].x[t], 0.f);
            wmma::store_matrix_sync(
                &C[(size_t)(m0 + wr * 64 + i * 16) * ldc + n0 + wc * 32 + j * 16],
                acc[i][j], ldc, wmma::mem_row_major);
        }
}

// ---- LSTM elementwise + output dot ----
__global__ void lstm_kernel(const float* __restrict__ cell, const float* __restrict__ Wout,
                            const float* __restrict__ bout,
                            float* __restrict__ out_output, float* __restrict__ out_h,
                            float* __restrict__ out_c) {
    int b = blockIdx.x, j = threadIdx.x;   // 512 threads
    const float* g = g_gates + (size_t)b * 2048;
    float gi = g[j], gf = g[512 + j], gg = g[1024 + j], go = g[1536 + j];
    float c_old = cell[(size_t)b * HH + j];
    float si = 1.f / (1.f + expf(-gi));
    float sf = 1.f / (1.f + expf(-gf));
    float so = 1.f / (1.f + expf(-go));
    float tg = tanhf(gg);
    float cn = sf * c_old + si * tg;
    float hn = so * tanhf(cn);
    out_c[(size_t)b * HH + j] = cn;
    out_h[(size_t)b * HH + j] = hn;

    float part = hn * Wout[j];
#pragma unroll
    for (int off = 16; off; off >>= 1) part += __shfl_down_sync(0xffffffffu, part, off);
    __shared__ float sp[16];
    if ((j & 31) == 0) sp[j >> 5] = part;
    __syncthreads();
    if (j < 16) {
        float v = sp[j];
#pragma unroll
        for (int off = 8; off; off >>= 1) v += __shfl_down_sync(0xffffu, v, off);
        if (j == 0) out_output[b] = v + bout[0];
    }
}

extern "C" void kernel_launch(void* const* d_in, const int* in_sizes, int n_in,
                              void* d_out, int out_size) {
    const float* input  = (const float*)d_in[0];
    const float* hidden = (const float*)d_in[1];
    const float* cell   = (const float*)d_in[2];
    const float* enc    = (const float*)d_in[3];
    const float* Wattn  = (const float*)d_in[4];
    const float* battn  = (const float*)d_in[5];
    const float* Wcomb  = (const float*)d_in[6];
    const float* bcomb  = (const float*)d_in[7];
    const float* Wih    = (const float*)d_in[8];
    const float* Whh    = (const float*)d_in[9];
    const float* bih    = (const float*)d_in[10];
    const float* bhh    = (const float*)d_in[11];
    const float* Wout   = (const float*)d_in[12];
    const float* bout   = (const float*)d_in[13];

    int B = in_sizes[1] / HH;   // 16384

    float* out      = (float*)d_out;
    float* o_output = out;                              // [B, 1]
    float* o_h      = out + (size_t)B;                  // [B, H]
    float* o_c      = o_h + (size_t)B * HH;             // [B, H]
    float* o_aw     = o_c + (size_t)B * HH;             // [B, 1, S]

    float *pXc, *pAbig, *pGates, *pWc, *pWg;
    cudaGetSymbolAddress((void**)&pXc,    g_Xc);
    cudaGetSymbolAddress((void**)&pAbig,  g_Abig);
    cudaGetSymbolAddress((void**)&pGates, g_gates);
    cudaGetSymbolAddress((void**)&pWc,    g_Wc);
    cudaGetSymbolAddress((void**)&pWg,    g_Wg);

    constexpr int SMEMB = 2 * 2 * 128 * 36 * (int)sizeof(float);   // 73728
    cudaFuncSetAttribute(gemm_tf32<true>,  cudaFuncAttributeMaxDynamicSharedMemorySize, SMEMB);
    cudaFuncSetAttribute(gemm_tf32<false>, cudaFuncAttributeMaxDynamicSharedMemorySize, SMEMB);

    init_weights<<<512, 256>>>(Wcomb, bcomb, Wih, Whh, bih, bhh);
    attn_kernel<<<B, 256>>>(input, hidden, cell, enc, Wattn, battn, o_aw);

    // comb: Abig[:, 0:512] = relu(Xc @ Wc^T)   (input col + bias folded into K)
    {
        dim3 grid(HH / 128, B / 128);
        gemm_tf32<true><<<grid, 256, SMEMB>>>(pXc, KC, pWc, KC, pAbig, KG, KC);
    }
    // gates = Abig @ Wg^T   ([x | hidden | 1] against [W_ih | W_hh | b_ih+b_hh])
    {
        dim3 grid((4 * HH) / 128, B / 128);
        gemm_tf32<false><<<grid, 256, SMEMB>>>(pAbig, KG, pWg, KG, pGates, 4 * HH, KG);
    }
    lstm_kernel<<<B, 512>>>(cell, Wout, bout, o_output, o_h, o_c);
}